// round 3
// baseline (speedup 1.0000x reference)
#include <cuda_runtime.h>
#include <cuda_bf16.h>
#include <math.h>
#include <stdint.h>

// ----------------------------------------------------------------------------
// Problem constants (fixed shapes from metadata)
// ----------------------------------------------------------------------------
#define TT   2048
#define BB   32
#define II   512
#define HH   512
#define GW   3072            // 6 * H  (gr_f, gc_f, gn_f, gr_b, gc_b, gn_b)

// Recurrence kernel geometry
#define NB    64             // blocks per direction
#define CPB   8              // hidden columns per block (64*8 = 512)
#define WPAD  516            // padded SMEM row stride (bank-conflict free, 16B aligned)

// ----------------------------------------------------------------------------
// Device scratch (static __device__ arrays: allocation-free)
// ----------------------------------------------------------------------------
__device__ float   g_G[(size_t)TT * BB * GW];      // 805 MB gate pre-activations
__device__ float   g_h[2][2][BB * HH];             // [dir][parity][b*H + j]
__device__ unsigned g_cnt[2] = {0u, 0u};           // barrier arrival counters
__device__ unsigned g_gen[2] = {0u, 0u};           // barrier generations (monotonic)

// ----------------------------------------------------------------------------
// Kernel A: input projection GEMM
//   G[m, mat*512 + n] = x[m, :] @ W[mat][:, n] + bias[mat][n]
//   m = t*B + b, mats: 0..5 = {Wri_f, Wci_f, Wni_f, Wri_b, Wci_b, Wni_b}
//   BM=128, BN=64, BK=16, 256 threads, 8x4 micro-tile, register prefetch.
// ----------------------------------------------------------------------------
struct GemmArgs {
    const float* W[6];
    const float* bias[6];
};

__global__ void __launch_bounds__(256) in_gemm(const float* __restrict__ x, GemmArgs ga)
{
    __shared__ float As[16][132];   // [k][m], padded (132*4 % 16 == 0)
    __shared__ float Bs[16][68];    // [k][n], padded

    const int tid = threadIdx.x;
    const int mat = blockIdx.x >> 3;          // which of the 6 weight matrices
    const int n0  = (blockIdx.x & 7) * 64;    // column offset within that matrix
    const int m0  = blockIdx.y * 128;

    const float* Wm = ga.W[mat];

    const int tx = tid & 15;        // 0..15 -> 4 output cols
    const int ty = tid >> 4;        // 0..15 -> 8 output rows

    // A-tile load mapping: 128 rows x 16 k, 8 floats (2 x float4) per thread
    const int rowA = tid >> 1;             // 0..127
    const int colA = (tid & 1) * 8;        // 0 or 8
    // B-tile load mapping: 16 rows x 64 cols, 1 float4 per thread
    const int rB = tid >> 4;               // 0..15
    const int cB = (tid & 15) * 4;         // 0..60

    const float* ap = x  + (size_t)(m0 + rowA) * II + colA;
    const float* bp = Wm + (size_t)rB * HH + n0 + cB;

    float4 a0 = *(const float4*)(ap);
    float4 a1 = *(const float4*)(ap + 4);
    float4 b0 = *(const float4*)(bp);

    float acc[8][4];
    #pragma unroll
    for (int i = 0; i < 8; ++i)
        #pragma unroll
        for (int jj = 0; jj < 4; ++jj) acc[i][jj] = 0.0f;

    #pragma unroll 1
    for (int kt = 0; kt < 32; ++kt) {
        // commit prefetched tile to SMEM
        As[colA + 0][rowA] = a0.x;
        As[colA + 1][rowA] = a0.y;
        As[colA + 2][rowA] = a0.z;
        As[colA + 3][rowA] = a0.w;
        As[colA + 4][rowA] = a1.x;
        As[colA + 5][rowA] = a1.y;
        As[colA + 6][rowA] = a1.z;
        As[colA + 7][rowA] = a1.w;
        *(float4*)&Bs[rB][cB] = b0;
        __syncthreads();

        if (kt < 31) {               // prefetch next K-tile (overlaps compute)
            ap += 16;
            bp += (size_t)16 * HH;
            a0 = *(const float4*)(ap);
            a1 = *(const float4*)(ap + 4);
            b0 = *(const float4*)(bp);
        }

        #pragma unroll
        for (int k = 0; k < 16; ++k) {
            float4 bb  = *(const float4*)&Bs[k][tx * 4];
            float4 aa0 = *(const float4*)&As[k][ty * 8];
            float4 aa1 = *(const float4*)&As[k][ty * 8 + 4];
            float av[8] = {aa0.x, aa0.y, aa0.z, aa0.w, aa1.x, aa1.y, aa1.z, aa1.w};
            float bv[4] = {bb.x, bb.y, bb.z, bb.w};
            #pragma unroll
            for (int i = 0; i < 8; ++i)
                #pragma unroll
                for (int jj = 0; jj < 4; ++jj)
                    acc[i][jj] += av[i] * bv[jj];
        }
        __syncthreads();
    }

    const float4 bias4 = *(const float4*)(ga.bias[mat] + n0 + tx * 4);
    const size_t ncol = (size_t)mat * 512 + n0 + tx * 4;
    #pragma unroll
    for (int i = 0; i < 8; ++i) {
        size_t m = (size_t)m0 + ty * 8 + i;
        float4 v;
        v.x = acc[i][0] + bias4.x;
        v.y = acc[i][1] + bias4.y;
        v.z = acc[i][2] + bias4.z;
        v.w = acc[i][3] + bias4.w;
        *(float4*)&g_G[m * GW + ncol] = v;
    }
}

// ----------------------------------------------------------------------------
// Kernel B: persistent bidirectional recurrence
// ----------------------------------------------------------------------------
struct RecArgs {
    const float* Wrh[2];
    const float* Wch[2];
    const float* Wnh[2];
    const float* bnh[2];
    float*       out;
};

// Per-direction grid barrier across NB blocks. `gen` is monotonic across
// launches (work is launch-invariant); base is the launch-start value.
__device__ __forceinline__ void dir_barrier(int d, unsigned base, unsigned target)
{
    __syncthreads();
    if (threadIdx.x == 0) {
        __threadfence();                       // publish prior global writes
        unsigned arr = atomicAdd(&g_cnt[d], 1u);
        if (arr == (unsigned)(NB - 1)) {
            atomicExch(&g_cnt[d], 0u);
            __threadfence();
            atomicAdd(&g_gen[d], 1u);
        } else {
            while ((*(volatile unsigned*)&g_gen[d]) - base < target) { }
        }
        __threadfence();                       // acquire + L1 invalidate (membar.gl)
    }
    __syncthreads();
}

__global__ void __launch_bounds__(256, 1) gru_recur(RecArgs p)
{
    extern __shared__ float smem[];
    float* Wt = smem;                          // [3][CPB][WPAD] transposed weight slice
    float* hs = smem + 3 * CPB * WPAD;         // [BB][WPAD] staged hidden state

    const int tid = threadIdx.x;
    const int dir = blockIdx.x / NB;           // 0 = forward, 1 = backward
    const int blk = blockIdx.x % NB;
    const int b   = tid >> 3;                  // batch row 0..31
    const int j   = tid & 7;                   // local column 0..7
    const int j0  = blk * CPB;

    __shared__ unsigned s_base;
    if (tid == 0) s_base = *(volatile unsigned*)&g_gen[dir];

    // Load this block's 512x8 weight slice, transposed: Wt[g][jj][k]
    {
        const float* Wsrc0 = p.Wrh[dir];
        const float* Wsrc1 = p.Wch[dir];
        const float* Wsrc2 = p.Wnh[dir];
        for (int idx = tid; idx < 3 * HH * CPB; idx += 256) {
            int g   = idx >> 12;               // / (512*8)
            int rem = idx & 4095;
            int k   = rem >> 3;
            int jj  = rem & 7;
            const float* src = (g == 0) ? Wsrc0 : (g == 1) ? Wsrc1 : Wsrc2;
            Wt[(g * CPB + jj) * WPAD + k] = src[(size_t)k * HH + j0 + jj];
        }
    }
    const float mybnh = p.bnh[dir][j0 + j];

    // h0 = 0 (parity 0); every launch re-initializes -> deterministic
    g_h[dir][0][b * HH + j0 + j] = 0.0f;
    __syncthreads();
    const unsigned base = s_base;
    unsigned nbar = 1;
    dir_barrier(dir, base, nbar);

    const float* wr = &Wt[(0 * CPB + j) * WPAD];
    const float* wc = &Wt[(1 * CPB + j) * WPAD];
    const float* wn = &Wt[(2 * CPB + j) * WPAD];
    float* out = p.out;

    for (int s = 0; s < TT; ++s) {
        const int t = dir ? (TT - 1 - s) : s;

        // Issue gate pre-activation loads early (latency hidden by h staging + GEMM)
        const size_t gbase = ((size_t)t * BB + b) * GW + (size_t)dir * 1536 + (j0 + j);
        const float gr = g_G[gbase];
        const float gc = g_G[gbase + 512];
        const float gn = g_G[gbase + 1024];

        // Stage full h (32x512) into SMEM; __ldcv bypasses L1 (cross-SM producer)
        const int par = s & 1;
        const float4* hsrc = (const float4*)g_h[dir][par];
        #pragma unroll
        for (int r = 0; r < 16; ++r) {
            int idx = tid + r * 256;           // 4096 float4s total
            float4 v = __ldcv(hsrc + idx);
            int bb = idx >> 7;
            int kk = (idx & 127) << 2;
            *(float4*)&hs[bb * WPAD + kk] = v;
        }
        __syncthreads();

        // Three dot products of length 512 (r/c/n gates) for this (b, j)
        float ar = 0.f, ac = 0.f, an = 0.f;
        const float* hr = &hs[b * WPAD];
        #pragma unroll 8
        for (int k = 0; k < HH; k += 4) {
            float4 hv = *(const float4*)&hr[k];
            float4 r4 = *(const float4*)&wr[k];
            float4 c4 = *(const float4*)&wc[k];
            float4 n4 = *(const float4*)&wn[k];
            ar += hv.x * r4.x;  ac += hv.x * c4.x;  an += hv.x * n4.x;
            ar += hv.y * r4.y;  ac += hv.y * c4.y;  an += hv.y * n4.y;
            ar += hv.z * r4.z;  ac += hv.z * c4.z;  an += hv.z * n4.z;
            ar += hv.w * r4.w;  ac += hv.w * c4.w;  an += hv.w * n4.w;
        }

        const float rg   = 1.0f / (1.0f + __expf(-(gr + ar)));
        const float cg   = 1.0f / (1.0f + __expf(-(gc + ac)));
        const float ng   = tanhf(gn + rg * (an + mybnh));
        const float hold = hr[j0 + j];
        const float hnew = ng + cg * (hold - ng);

        g_h[dir][par ^ 1][b * HH + j0 + j] = hnew;
        out[((size_t)t * BB + b) * (2 * HH) + dir * HH + (j0 + j)] = hnew;

        ++nbar;
        dir_barrier(dir, base, nbar);
    }
}

// ----------------------------------------------------------------------------
// Launch
// Input order: x, Wri_f,Wci_f,Wni_f,Wrh_f,Wch_f,Wnh_f,br_f,bi_f,bni_f,bnh_f,
//              Wri_b,Wci_b,Wni_b,Wrh_b,Wch_b,Wnh_b,br_b,bi_b,bni_b,bnh_b
// ----------------------------------------------------------------------------
extern "C" void kernel_launch(void* const* d_in, const int* in_sizes, int n_in,
                              void* d_out, int out_size)
{
    (void)in_sizes; (void)n_in; (void)out_size;
    const float* x = (const float*)d_in[0];

    GemmArgs ga;
    ga.W[0] = (const float*)d_in[1];   // Wri_f
    ga.W[1] = (const float*)d_in[2];   // Wci_f
    ga.W[2] = (const float*)d_in[3];   // Wni_f
    ga.W[3] = (const float*)d_in[11];  // Wri_b
    ga.W[4] = (const float*)d_in[12];  // Wci_b
    ga.W[5] = (const float*)d_in[13];  // Wni_b
    ga.bias[0] = (const float*)d_in[7];   // br_f
    ga.bias[1] = (const float*)d_in[8];   // bi_f
    ga.bias[2] = (const float*)d_in[9];   // bni_f
    ga.bias[3] = (const float*)d_in[17];  // br_b
    ga.bias[4] = (const float*)d_in[18];  // bi_b
    ga.bias[5] = (const float*)d_in[19];  // bni_b

    RecArgs ra;
    ra.Wrh[0] = (const float*)d_in[4];   ra.Wrh[1] = (const float*)d_in[14];
    ra.Wch[0] = (const float*)d_in[5];   ra.Wch[1] = (const float*)d_in[15];
    ra.Wnh[0] = (const float*)d_in[6];   ra.Wnh[1] = (const float*)d_in[16];
    ra.bnh[0] = (const float*)d_in[10];  ra.bnh[1] = (const float*)d_in[20];
    ra.out = (float*)d_out;

    // Kernel A: input projections -> g_G
    dim3 ggrid(48, 512);
    in_gemm<<<ggrid, 256>>>(x, ga);

    // Kernel B: persistent recurrence (128 CTAs, all co-resident: grid <= #SMs,
    // 1 CTA/SM via launch bounds). ~113 KB dynamic SMEM.
    const int rsmem = (3 * CPB * WPAD + BB * WPAD) * (int)sizeof(float);
    cudaFuncSetAttribute(gru_recur, cudaFuncAttributeMaxDynamicSharedMemorySize, rsmem);
    gru_recur<<<2 * NB, 256, rsmem>>>(ra);
}

// round 4
// speedup vs baseline: 1.1191x; 1.1191x over previous
#include <cuda_runtime.h>
#include <cuda_bf16.h>
#include <math.h>
#include <stdint.h>

// ----------------------------------------------------------------------------
// Problem constants
// ----------------------------------------------------------------------------
#define TT   2048
#define BB   32
#define II   512
#define HH   512
#define GW   3072            // 6 * H

// Recurrence geometry: 64 CTAs per direction, 8 hidden cols per CTA,
// 512 threads: tile = 4 batch x 6 (j,gate), 16-way k-split.
#define NB    64
#define CPB   8
#define WPAD  516            // padded row stride (floats)

// ----------------------------------------------------------------------------
// Device scratch
// ----------------------------------------------------------------------------
__device__ float    g_G[(size_t)TT * BB * GW];     // gate pre-activations
__device__ float    g_h[2][2][BB * HH];            // [dir][parity]
__device__ unsigned g_cnt[2] = {0u, 0u};
__device__ unsigned g_gen[2] = {0u, 0u};

// ----------------------------------------------------------------------------
// Kernel A: input projection GEMM (unchanged from R2 — near fp32 SIMT floor)
// ----------------------------------------------------------------------------
struct GemmArgs {
    const float* W[6];
    const float* bias[6];
};

__global__ void __launch_bounds__(256) in_gemm(const float* __restrict__ x, GemmArgs ga)
{
    __shared__ float As[16][132];
    __shared__ float Bs[16][68];

    const int tid = threadIdx.x;
    const int mat = blockIdx.x >> 3;
    const int n0  = (blockIdx.x & 7) * 64;
    const int m0  = blockIdx.y * 128;

    const float* Wm = ga.W[mat];

    const int tx = tid & 15;
    const int ty = tid >> 4;

    const int rowA = tid >> 1;
    const int colA = (tid & 1) * 8;
    const int rB = tid >> 4;
    const int cB = (tid & 15) * 4;

    const float* ap = x  + (size_t)(m0 + rowA) * II + colA;
    const float* bp = Wm + (size_t)rB * HH + n0 + cB;

    float4 a0 = *(const float4*)(ap);
    float4 a1 = *(const float4*)(ap + 4);
    float4 b0 = *(const float4*)(bp);

    float acc[8][4];
    #pragma unroll
    for (int i = 0; i < 8; ++i)
        #pragma unroll
        for (int jj = 0; jj < 4; ++jj) acc[i][jj] = 0.0f;

    #pragma unroll 1
    for (int kt = 0; kt < 32; ++kt) {
        As[colA + 0][rowA] = a0.x;
        As[colA + 1][rowA] = a0.y;
        As[colA + 2][rowA] = a0.z;
        As[colA + 3][rowA] = a0.w;
        As[colA + 4][rowA] = a1.x;
        As[colA + 5][rowA] = a1.y;
        As[colA + 6][rowA] = a1.z;
        As[colA + 7][rowA] = a1.w;
        *(float4*)&Bs[rB][cB] = b0;
        __syncthreads();

        if (kt < 31) {
            ap += 16;
            bp += (size_t)16 * HH;
            a0 = *(const float4*)(ap);
            a1 = *(const float4*)(ap + 4);
            b0 = *(const float4*)(bp);
        }

        #pragma unroll
        for (int k = 0; k < 16; ++k) {
            float4 bb  = *(const float4*)&Bs[k][tx * 4];
            float4 aa0 = *(const float4*)&As[k][ty * 8];
            float4 aa1 = *(const float4*)&As[k][ty * 8 + 4];
            float av[8] = {aa0.x, aa0.y, aa0.z, aa0.w, aa1.x, aa1.y, aa1.z, aa1.w};
            float bv[4] = {bb.x, bb.y, bb.z, bb.w};
            #pragma unroll
            for (int i = 0; i < 8; ++i)
                #pragma unroll
                for (int jj = 0; jj < 4; ++jj)
                    acc[i][jj] += av[i] * bv[jj];
        }
        __syncthreads();
    }

    const float4 bias4 = *(const float4*)(ga.bias[mat] + n0 + tx * 4);
    const size_t ncol = (size_t)mat * 512 + n0 + tx * 4;
    #pragma unroll
    for (int i = 0; i < 8; ++i) {
        size_t m = (size_t)m0 + ty * 8 + i;
        float4 v;
        v.x = acc[i][0] + bias4.x;
        v.y = acc[i][1] + bias4.y;
        v.z = acc[i][2] + bias4.z;
        v.w = acc[i][3] + bias4.w;
        *(float4*)&g_G[m * GW + ncol] = v;
    }
}

// ----------------------------------------------------------------------------
// Kernel B: persistent bidirectional recurrence (register-tiled)
// ----------------------------------------------------------------------------
struct RecArgs {
    const float* Wrh[2];
    const float* Wch[2];
    const float* Wnh[2];
    const float* bnh[2];
    float*       out;
};

__device__ __forceinline__ void dir_barrier(int d, unsigned base, unsigned target)
{
    __syncthreads();
    if (threadIdx.x == 0) {
        __threadfence();
        unsigned arr = atomicAdd(&g_cnt[d], 1u);
        if (arr == (unsigned)(NB - 1)) {
            atomicExch(&g_cnt[d], 0u);
            __threadfence();
            atomicAdd(&g_gen[d], 1u);
        } else {
            while ((*(volatile unsigned*)&g_gen[d]) - base < target) { }
        }
        __threadfence();
    }
    __syncthreads();
}

__global__ void __launch_bounds__(512, 1) gru_recur(RecArgs p)
{
    extern __shared__ float smem[];
    float* Wt = smem;                          // [24][WPAD]  rows: jl*3 + gate
    float* hs = Wt + 24 * WPAD;                // [BB][WPAD]  staged hidden state
    float* gs = hs + BB * WPAD;                // [BB*CPB*3]  staged gate preacts

    const int tid = threadIdx.x;
    const int dir = blockIdx.x / NB;
    const int blk = blockIdx.x % NB;

    // thread tile mapping: s = k-split lane (0..15), jgg = j-pair (0..3), bg = b-group (0..7)
    const int s   = tid & 15;
    const int jgg = (tid >> 4) & 3;
    const int bg  = tid >> 6;
    const int b0  = bg * 4;
    const int j0  = blk * CPB;

    __shared__ unsigned s_base;
    if (tid == 0) s_base = *(volatile unsigned*)&g_gen[dir];

    // Load + transpose weight slice: Wt[jl*3+g][k] = W_g[k][j0+jl]
    {
        const float* Wsrc0 = p.Wrh[dir];
        const float* Wsrc1 = p.Wch[dir];
        const float* Wsrc2 = p.Wnh[dir];
        for (int idx = tid; idx < 3 * HH * CPB; idx += 512) {
            int g   = idx >> 12;
            int rem = idx & 4095;
            int k   = rem >> 3;
            int jl  = rem & 7;
            const float* src = (g == 0) ? Wsrc0 : (g == 1) ? Wsrc1 : Wsrc2;
            Wt[(jl * 3 + g) * WPAD + k] = src[(size_t)k * HH + j0 + jl];
        }
    }

    // bias(nh) for this thread's 2 columns
    float mybnh[2];
    mybnh[0] = p.bnh[dir][j0 + jgg * 2 + 0];
    mybnh[1] = p.bnh[dir][j0 + jgg * 2 + 1];

    // h0 = 0 (parity 0): each CTA zeroes its own 8 columns x 32 b
    if (tid < 256) {
        int b  = tid >> 3;
        int jl = tid & 7;
        g_h[dir][0][b * HH + j0 + jl] = 0.0f;
    }
    __syncthreads();
    const unsigned base = s_base;
    unsigned nbar = 1;
    dir_barrier(dir, base, nbar);

    const float* wbase = &Wt[(jgg * 6) * WPAD];  // 6 rows: (jj,g)
    const float* hbase = &hs[b0 * WPAD];         // 4 rows: b0..b0+3
    float* out = p.out;

    for (int st = 0; st < TT; ++st) {
        const int t   = dir ? (TT - 1 - st) : st;
        const int par = st & 1;

        // Stage h (32x512) into SMEM; __ldcv bypasses L1 (cross-SM producers)
        {
            const float4* hsrc = (const float4*)g_h[dir][par];
            #pragma unroll
            for (int r = 0; r < 8; ++r) {
                int idx = tid + r * 512;             // 4096 float4s
                float4 v = __ldcv(hsrc + idx);
                int bb = idx >> 7;
                int kk = (idx & 127) << 2;
                *(float4*)&hs[bb * WPAD + kk] = v;
            }
        }
        // Stage this CTA's gate pre-activations (32b x 8j x 3g = 768 floats)
        {
            const size_t trow = (size_t)t * BB;
            for (int idx = tid; idx < BB * CPB * 3; idx += 512) {
                int b  = idx / 24;
                int r  = idx - b * 24;
                int jl = r / 3;
                int g  = r - jl * 3;
                gs[idx] = __ldg(&g_G[(trow + b) * GW + (size_t)dir * 1536 +
                                     (size_t)g * 512 + (j0 + jl)]);
            }
        }
        __syncthreads();

        // 4b x 6(j,g) register tile, 16-way interleaved k-split
        float acc[4][6];
        #pragma unroll
        for (int bb = 0; bb < 4; ++bb)
            #pragma unroll
            for (int r = 0; r < 6; ++r) acc[bb][r] = 0.0f;

        #pragma unroll
        for (int i = 0; i < 8; ++i) {
            const int kk = (s << 2) + (i << 6);
            float4 hv[4];
            #pragma unroll
            for (int bb = 0; bb < 4; ++bb)
                hv[bb] = *(const float4*)&hbase[bb * WPAD + kk];
            float4 wv[6];
            #pragma unroll
            for (int r = 0; r < 6; ++r)
                wv[r] = *(const float4*)&wbase[r * WPAD + kk];
            #pragma unroll
            for (int bb = 0; bb < 4; ++bb)
                #pragma unroll
                for (int r = 0; r < 6; ++r) {
                    acc[bb][r] += hv[bb].x * wv[r].x;
                    acc[bb][r] += hv[bb].y * wv[r].y;
                    acc[bb][r] += hv[bb].z * wv[r].z;
                    acc[bb][r] += hv[bb].w * wv[r].w;
                }
        }

        // butterfly reduce over the 16 k-split lanes (lane bits 0..3)
        #pragma unroll
        for (int m = 1; m < 16; m <<= 1)
            #pragma unroll
            for (int bb = 0; bb < 4; ++bb)
                #pragma unroll
                for (int r = 0; r < 6; ++r)
                    acc[bb][r] += __shfl_xor_sync(0xffffffffu, acc[bb][r], m);

        // epilogue: one lane per tile computes 4b x 2j outputs
        if (s == 0) {
            #pragma unroll
            for (int bb = 0; bb < 4; ++bb) {
                const int b = b0 + bb;
                #pragma unroll
                for (int jj = 0; jj < 2; ++jj) {
                    const int jl   = jgg * 2 + jj;
                    const int jcol = j0 + jl;
                    const float ar = acc[bb][jj * 3 + 0];
                    const float ac = acc[bb][jj * 3 + 1];
                    const float an = acc[bb][jj * 3 + 2];
                    const float gr = gs[b * 24 + jl * 3 + 0];
                    const float gc = gs[b * 24 + jl * 3 + 1];
                    const float gn = gs[b * 24 + jl * 3 + 2];
                    const float rg = 1.0f / (1.0f + __expf(-(gr + ar)));
                    const float cg = 1.0f / (1.0f + __expf(-(gc + ac)));
                    const float ng = tanhf(gn + rg * (an + mybnh[jj]));
                    const float hold = hs[b * WPAD + jcol];
                    const float hnew = ng + cg * (hold - ng);
                    g_h[dir][par ^ 1][b * HH + jcol] = hnew;
                    out[((size_t)t * BB + b) * (2 * HH) + dir * HH + jcol] = hnew;
                }
            }
        }

        ++nbar;
        dir_barrier(dir, base, nbar);
    }
}

// ----------------------------------------------------------------------------
// Launch
// ----------------------------------------------------------------------------
extern "C" void kernel_launch(void* const* d_in, const int* in_sizes, int n_in,
                              void* d_out, int out_size)
{
    (void)in_sizes; (void)n_in; (void)out_size;
    const float* x = (const float*)d_in[0];

    GemmArgs ga;
    ga.W[0] = (const float*)d_in[1];
    ga.W[1] = (const float*)d_in[2];
    ga.W[2] = (const float*)d_in[3];
    ga.W[3] = (const float*)d_in[11];
    ga.W[4] = (const float*)d_in[12];
    ga.W[5] = (const float*)d_in[13];
    ga.bias[0] = (const float*)d_in[7];
    ga.bias[1] = (const float*)d_in[8];
    ga.bias[2] = (const float*)d_in[9];
    ga.bias[3] = (const float*)d_in[17];
    ga.bias[4] = (const float*)d_in[18];
    ga.bias[5] = (const float*)d_in[19];

    RecArgs ra;
    ra.Wrh[0] = (const float*)d_in[4];   ra.Wrh[1] = (const float*)d_in[14];
    ra.Wch[0] = (const float*)d_in[5];   ra.Wch[1] = (const float*)d_in[15];
    ra.Wnh[0] = (const float*)d_in[6];   ra.Wnh[1] = (const float*)d_in[16];
    ra.bnh[0] = (const float*)d_in[10];  ra.bnh[1] = (const float*)d_in[20];
    ra.out = (float*)d_out;

    dim3 ggrid(48, 512);
    in_gemm<<<ggrid, 256>>>(x, ga);

    const int rsmem = (24 * WPAD + BB * WPAD + BB * CPB * 3) * (int)sizeof(float);
    cudaFuncSetAttribute(gru_recur, cudaFuncAttributeMaxDynamicSharedMemorySize, rsmem);
    gru_recur<<<2 * NB, 512, rsmem>>>(ra);
}

// round 5
// speedup vs baseline: 1.5710x; 1.4039x over previous
#include <cuda_runtime.h>
#include <math.h>
#include <stdint.h>

// ----------------------------------------------------------------------------
// Problem constants
// ----------------------------------------------------------------------------
#define TT   2048
#define BB   32
#define HH   512
#define NB   64              // CTAs per direction
#define CPB  8               // hidden columns per CTA
#define STR  516             // SMEM row stride in floats (16B aligned, offset banks)

// ----------------------------------------------------------------------------
// Device scratch (no big g_G anymore — input projections computed in-kernel)
// ----------------------------------------------------------------------------
__device__ float    g_h[2][2][BB * HH];    // [dir][parity][b*H + j]
__device__ unsigned g_cnt[2] = {0u, 0u};
__device__ unsigned g_gen[2] = {0u, 0u};

struct Args {
    const float* x;
    const float* Wxi[2][3];   // [dir][{Wri,Wci,Wni}]  (I x H, row-major)
    const float* Whh[2][3];   // [dir][{Wrh,Wch,Wnh}]  (H x H, row-major)
    const float* br[2];
    const float* bi[2];
    const float* bni[2];
    const float* bnh[2];
    float*       out;
};

// Packed fp32x2 FMA (sm_100+/sm_103a): d = a*b + d, two fp32 lanes per inst.
__device__ __forceinline__ void ffma2(unsigned long long& d,
                                      unsigned long long a, unsigned long long b)
{
    asm("fma.rn.f32x2 %0, %1, %2, %0;" : "+l"(d) : "l"(a), "l"(b));
}

__device__ __forceinline__ float u64lo(unsigned long long v) {
    return __uint_as_float((unsigned)(v & 0xffffffffull));
}
__device__ __forceinline__ float u64hi(unsigned long long v) {
    return __uint_as_float((unsigned)(v >> 32));
}

// Split grid barrier (per direction). Arrive at end of step; wait mid-step.
// gen is monotonic across launches; `base` is captured at kernel start.
__device__ __forceinline__ void bar_arrive(int d)
{
    if (threadIdx.x == 0) {
        __threadfence();
        unsigned a = atomicAdd(&g_cnt[d], 1u);
        if (a == (unsigned)(NB - 1)) {
            atomicExch(&g_cnt[d], 0u);
            __threadfence();
            atomicAdd(&g_gen[d], 1u);
        }
    }
}
__device__ __forceinline__ void bar_wait(int d, unsigned base, unsigned target)
{
    if (threadIdx.x == 0) {
        while ((*(volatile unsigned*)&g_gen[d]) - base < target) { }
        __threadfence();
    }
    __syncthreads();
}

// ----------------------------------------------------------------------------
// Fused persistent kernel: per CTA, per step:
//   stage x(t) -> x-GEMM (hides barrier) -> wait h -> stage h -> h-GEMM
//   -> targeted reduce -> activations -> write h_new + output
// Thread tile: 8 batch x 2 cols x 4 channels {r, c, n_x, n_h}, 16-way k-split,
// all FMAs packed f32x2 over k-pairs.
// ----------------------------------------------------------------------------
__global__ void __launch_bounds__(256, 1) gru_fused(Args p)
{
    extern __shared__ float smem[];
    float* Wx  = smem;                 // [24][STR]  rows: jl*3 + gate
    float* Wh  = Wx + 24 * STR;        // [24][STR]
    float* buf = Wh + 24 * STR;        // [32][STR]  shared stage: x(t) then h(t)

    const int tid = threadIdx.x;
    const int dir = blockIdx.x / NB;
    const int blk = blockIdx.x % NB;
    const int j0  = blk * CPB;

    // tile mapping: s = k-split lane (0..15); 16 tiles; warp-adjacent tiles
    // share jp so weight reads broadcast across warp halves.
    const int s    = tid & 15;
    const int tt   = tid >> 4;
    const int jp   = (tt >> 1) & 3;                 // j-pair 0..3
    const int bsel = (tt & 1) | ((tt >> 3) << 1);   // 0..3
    const int b0   = bsel * 8;

    __shared__ unsigned s_base;
    if (tid == 0) s_base = *(volatile unsigned*)&g_gen[dir];

    // Load + transpose weight slices: W*[jl*3+g][k] = W_g[k][j0+jl]
    for (int idx = tid; idx < 3 * HH * CPB; idx += 256) {
        int g  = idx >> 12;
        int k  = (idx >> 3) & (HH - 1);
        int jl = idx & 7;
        Wx[(jl * 3 + g) * STR + k] = p.Wxi[dir][g][(size_t)k * HH + j0 + jl];
        Wh[(jl * 3 + g) * STR + k] = p.Whh[dir][g][(size_t)k * HH + j0 + jl];
    }

    // each thread owns exactly one (b, j) output
    const int myb  = b0 + (s & 7);
    const int jcol = j0 + jp * 2 + (s >> 3);
    const float c_br  = p.br [dir][jcol];
    const float c_bi  = p.bi [dir][jcol];
    const float c_bni = p.bni[dir][jcol];
    const float c_bnh = p.bnh[dir][jcol];

    // h0 = 0 (parity 0)
    g_h[dir][0][myb * HH + jcol] = 0.0f;
    __syncthreads();
    const unsigned base = s_base;
    bar_arrive(dir);                      // signals h0 ready

    const float* WxB = &Wx[jp * 6 * STR];
    const float* WhB = &Wh[jp * 6 * STR];
    float* out = p.out;

    for (int st = 0; st < TT; ++st) {
        const int t   = dir ? (TT - 1 - st) : st;
        const int par = st & 1;

        // ---- stage x(t): 32 x 512 floats -> buf (no serial dependency) ----
        {
            const float4* xs = (const float4*)(p.x + (size_t)t * BB * HH);
            #pragma unroll
            for (int r = 0; r < 16; ++r) {
                int idx = tid + r * 256;
                float4 v = __ldg(xs + idx);
                int bb = idx >> 7;
                int kk = (idx & 127) << 2;
                *(float4*)&buf[bb * STR + kk] = v;
            }
        }
        __syncthreads();

        // accumulators: [bb][jj*4 + ch], ch: 0=r, 1=c, 2=n_x, 3=n_h
        unsigned long long acc[8][8];
        #pragma unroll
        for (int bb = 0; bb < 8; ++bb)
            #pragma unroll
            for (int q = 0; q < 8; ++q) acc[bb][q] = 0ull;

        // ---- x-part GEMM (channels r, c, n_x) ----
        #pragma unroll
        for (int i = 0; i < 8; ++i) {
            const int kk = (s << 2) + (i << 6);
            ulonglong2 w0 = *(const ulonglong2*)&WxB[0 * STR + kk];
            ulonglong2 w1 = *(const ulonglong2*)&WxB[1 * STR + kk];
            ulonglong2 w2 = *(const ulonglong2*)&WxB[2 * STR + kk];
            ulonglong2 w3 = *(const ulonglong2*)&WxB[3 * STR + kk];
            ulonglong2 w4 = *(const ulonglong2*)&WxB[4 * STR + kk];
            ulonglong2 w5 = *(const ulonglong2*)&WxB[5 * STR + kk];
            #pragma unroll
            for (int bb = 0; bb < 8; ++bb) {
                ulonglong2 hv = *(const ulonglong2*)&buf[(b0 + bb) * STR + kk];
                ffma2(acc[bb][0], hv.x, w0.x);  ffma2(acc[bb][0], hv.y, w0.y);
                ffma2(acc[bb][1], hv.x, w1.x);  ffma2(acc[bb][1], hv.y, w1.y);
                ffma2(acc[bb][2], hv.x, w2.x);  ffma2(acc[bb][2], hv.y, w2.y);
                ffma2(acc[bb][4], hv.x, w3.x);  ffma2(acc[bb][4], hv.y, w3.y);
                ffma2(acc[bb][5], hv.x, w4.x);  ffma2(acc[bb][5], hv.y, w4.y);
                ffma2(acc[bb][6], hv.x, w5.x);  ffma2(acc[bb][6], hv.y, w5.y);
            }
        }

        // ---- wait for h(t); the x-GEMM above hid the barrier latency ----
        bar_wait(dir, base, (unsigned)(st + 1));   // includes __syncthreads

        // ---- stage h(t) -> buf (L1-bypassing loads; producers are other SMs)
        {
            const float4* hsrc = (const float4*)g_h[dir][par];
            #pragma unroll
            for (int r = 0; r < 16; ++r) {
                int idx = tid + r * 256;
                float4 v = __ldcv(hsrc + idx);
                int bb = idx >> 7;
                int kk = (idx & 127) << 2;
                *(float4*)&buf[bb * STR + kk] = v;
            }
        }
        __syncthreads();

        // ---- h-part GEMM (channels r, c, n_h) ----
        #pragma unroll
        for (int i = 0; i < 8; ++i) {
            const int kk = (s << 2) + (i << 6);
            ulonglong2 w0 = *(const ulonglong2*)&WhB[0 * STR + kk];
            ulonglong2 w1 = *(const ulonglong2*)&WhB[1 * STR + kk];
            ulonglong2 w2 = *(const ulonglong2*)&WhB[2 * STR + kk];
            ulonglong2 w3 = *(const ulonglong2*)&WhB[3 * STR + kk];
            ulonglong2 w4 = *(const ulonglong2*)&WhB[4 * STR + kk];
            ulonglong2 w5 = *(const ulonglong2*)&WhB[5 * STR + kk];
            #pragma unroll
            for (int bb = 0; bb < 8; ++bb) {
                ulonglong2 hv = *(const ulonglong2*)&buf[(b0 + bb) * STR + kk];
                ffma2(acc[bb][0], hv.x, w0.x);  ffma2(acc[bb][0], hv.y, w0.y);
                ffma2(acc[bb][1], hv.x, w1.x);  ffma2(acc[bb][1], hv.y, w1.y);
                ffma2(acc[bb][3], hv.x, w2.x);  ffma2(acc[bb][3], hv.y, w2.y);
                ffma2(acc[bb][4], hv.x, w3.x);  ffma2(acc[bb][4], hv.y, w3.y);
                ffma2(acc[bb][5], hv.x, w4.x);  ffma2(acc[bb][5], hv.y, w4.y);
                ffma2(acc[bb][7], hv.x, w5.x);  ffma2(acc[bb][7], hv.y, w5.y);
            }
        }

        // ---- collapse f32x2 pairs -> f32 ----
        float a64[8][8];
        #pragma unroll
        for (int bb = 0; bb < 8; ++bb)
            #pragma unroll
            for (int q = 0; q < 8; ++q)
                a64[bb][q] = u64lo(acc[bb][q]) + u64hi(acc[bb][q]);

        // ---- targeted exchange reduction over the 16 k-split lanes ----
        // round 1 (mask 8): split jj; keep own jj set
        const bool hi8 = (s & 8) != 0;
        float r32[8][4];
        #pragma unroll
        for (int bb = 0; bb < 8; ++bb)
            #pragma unroll
            for (int ch = 0; ch < 4; ++ch) {
                float mine = hi8 ? a64[bb][4 + ch] : a64[bb][ch];
                float oth  = hi8 ? a64[bb][ch]     : a64[bb][4 + ch];
                r32[bb][ch] = mine + __shfl_xor_sync(0xffffffffu, oth, 8);
            }
        // round 2 (mask 4): split bb bit 2
        const bool hi4 = (s & 4) != 0;
        float r16[4][4];
        #pragma unroll
        for (int bl = 0; bl < 4; ++bl)
            #pragma unroll
            for (int ch = 0; ch < 4; ++ch) {
                float mine = hi4 ? r32[bl + 4][ch] : r32[bl][ch];
                float oth  = hi4 ? r32[bl][ch]     : r32[bl + 4][ch];
                r16[bl][ch] = mine + __shfl_xor_sync(0xffffffffu, oth, 4);
            }
        // round 3 (mask 2): split bb bit 1
        const bool hi2 = (s & 2) != 0;
        float r8[2][4];
        #pragma unroll
        for (int bl = 0; bl < 2; ++bl)
            #pragma unroll
            for (int ch = 0; ch < 4; ++ch) {
                float mine = hi2 ? r16[bl + 2][ch] : r16[bl][ch];
                float oth  = hi2 ? r16[bl][ch]     : r16[bl + 2][ch];
                r8[bl][ch] = mine + __shfl_xor_sync(0xffffffffu, oth, 2);
            }
        // round 4 (mask 1): split bb bit 0 -> each lane holds its (b, j)
        const bool hi1 = (s & 1) != 0;
        float r4v[4];
        #pragma unroll
        for (int ch = 0; ch < 4; ++ch) {
            float mine = hi1 ? r8[1][ch] : r8[0][ch];
            float oth  = hi1 ? r8[0][ch] : r8[1][ch];
            r4v[ch] = mine + __shfl_xor_sync(0xffffffffu, oth, 1);
        }

        // ---- activations + state update (one output per thread) ----
        const float gr = r4v[0] + c_br;
        const float gc = r4v[1] + c_bi;
        const float rg = 1.0f / (1.0f + __expf(-gr));
        const float cg = 1.0f / (1.0f + __expf(-gc));
        const float ng = tanhf(r4v[2] + c_bni + rg * (r4v[3] + c_bnh));
        const float hold = buf[myb * STR + jcol];   // h(t) still staged in buf
        const float hnew = ng + cg * (hold - ng);

        g_h[dir][par ^ 1][myb * HH + jcol] = hnew;
        out[((size_t)t * BB + myb) * (2 * HH) + dir * HH + jcol] = hnew;

        __syncthreads();
        bar_arrive(dir);
    }
}

// ----------------------------------------------------------------------------
// Launch. Input order: x, Wri_f,Wci_f,Wni_f,Wrh_f,Wch_f,Wnh_f,br_f,bi_f,bni_f,
// bnh_f, Wri_b,Wci_b,Wni_b,Wrh_b,Wch_b,Wnh_b,br_b,bi_b,bni_b,bnh_b
// ----------------------------------------------------------------------------
extern "C" void kernel_launch(void* const* d_in, const int* in_sizes, int n_in,
                              void* d_out, int out_size)
{
    (void)in_sizes; (void)n_in; (void)out_size;

    Args a;
    a.x = (const float*)d_in[0];
    a.Wxi[0][0] = (const float*)d_in[1];
    a.Wxi[0][1] = (const float*)d_in[2];
    a.Wxi[0][2] = (const float*)d_in[3];
    a.Whh[0][0] = (const float*)d_in[4];
    a.Whh[0][1] = (const float*)d_in[5];
    a.Whh[0][2] = (const float*)d_in[6];
    a.br [0] = (const float*)d_in[7];
    a.bi [0] = (const float*)d_in[8];
    a.bni[0] = (const float*)d_in[9];
    a.bnh[0] = (const float*)d_in[10];
    a.Wxi[1][0] = (const float*)d_in[11];
    a.Wxi[1][1] = (const float*)d_in[12];
    a.Wxi[1][2] = (const float*)d_in[13];
    a.Whh[1][0] = (const float*)d_in[14];
    a.Whh[1][1] = (const float*)d_in[15];
    a.Whh[1][2] = (const float*)d_in[16];
    a.br [1] = (const float*)d_in[17];
    a.bi [1] = (const float*)d_in[18];
    a.bni[1] = (const float*)d_in[19];
    a.bnh[1] = (const float*)d_in[20];
    a.out = (float*)d_out;

    const int smem = (48 * STR + 32 * STR) * (int)sizeof(float);   // ~165 KB
    cudaFuncSetAttribute(gru_fused, cudaFuncAttributeMaxDynamicSharedMemorySize, smem);
    gru_fused<<<2 * NB, 256, smem>>>(a);
}